// round 3
// baseline (speedup 1.0000x reference)
#include <cuda_runtime.h>
#include <cuda_bf16.h>

// ---------------------------------------------------------------------------
// RtoVMainModel: conv1(3->6,5x5)+relu+pool2 ; conv2(6->16,5x5)+relu+pool2 ;
// flatten(400) ; linear chains collapsed at runtime: T2 = W3@(W3... S=W3@W2,
// T2=S@W1 (skips 84x400 intermediate). Experts' final rows built in k_out.
// d_out layout: [shapes (B*4) | out (B*6)] float32
// ---------------------------------------------------------------------------

#define B_TOTAL 16384
typedef unsigned long long u64;

__device__ __forceinline__ u64 pk(float lo, float hi) {
    u64 r; asm("mov.b64 %0, {%1, %2};" : "=l"(r) : "f"(lo), "f"(hi)); return r;
}
__device__ __forceinline__ void upk(u64 p, float& lo, float& hi) {
    asm("mov.b64 {%0, %1}, %2;" : "=f"(lo), "=f"(hi) : "l"(p));
}
__device__ __forceinline__ u64 fma2(u64 a, u64 b, u64 c) {
    u64 d; asm("fma.rn.f32x2 %0, %1, %2, %3;" : "=l"(d) : "l"(a), "l"(b), "l"(c)); return d;
}

// scratch (device globals: no allocation allowed)
__device__ float g_T2[5 * 10 * 400];   // chain 0 = shapes head collapsed (10x400)
__device__ float g_b3[5 * 10];         // collapsed bias through layer 3
__device__ float g_xf[B_TOTAL * 400];  // flattened conv features
__device__ int   g_last[6 * 32];       // routing slots: [col][b&31]

// ---------------------------------------------------------------------------
// Prologue: one kernel. grid = 20 blocks (5 chains x 4 j-quarters), 256 thr.
// S = W3@W2 (10x120), T2[quarter] = S@W1, b2'=W2@b1+b2, b3'=W3@b2'+b3.
// ---------------------------------------------------------------------------
__global__ void __launch_bounds__(256)
kc_prep(const float* __restrict__ sw1, const float* __restrict__ sb1,
        const float* __restrict__ sw2, const float* __restrict__ sb2,
        const float* __restrict__ sw3, const float* __restrict__ sb3,
        const float* __restrict__ ew1, const float* __restrict__ eb1,
        const float* __restrict__ ew2, const float* __restrict__ eb2,
        const float* __restrict__ ew3, const float* __restrict__ eb3) {
    __shared__ float sW2[84 * 120];
    __shared__ float sS[10 * 120];
    __shared__ float sb2p[84];

    int chain = blockIdx.x >> 2, q = blockIdx.x & 3;
    int tid = threadIdx.x;
    if (blockIdx.x == 0 && tid < 192) g_last[tid] = -1;

    const float* W1 = chain ? (ew1 + (chain - 1) * 120 * 400) : sw1;
    const float* W2 = chain ? (ew2 + (chain - 1) * 84 * 120) : sw2;
    const float* W3 = chain ? (ew3 + (chain - 1) * 10 * 84) : sw3;
    const float* b1 = chain ? (eb1 + (chain - 1) * 120) : sb1;
    const float* b2 = chain ? (eb2 + (chain - 1) * 84) : sb2;
    const float* b3 = chain ? (eb3 + (chain - 1) * 10) : sb3;

    for (int i = tid; i < 10080; i += 256) sW2[i] = W2[i];
    __syncthreads();

    // S[o][k] = sum_m W3[o][m] * W2[m][k]
    for (int p = tid; p < 1200; p += 256) {
        int o = p / 120, k = p - o * 120;
        float s = 0.f;
        const float* w3r = W3 + o * 84;
        for (int m = 0; m < 84; m++) s = fmaf(w3r[m], sW2[m * 120 + k], s);
        sS[p] = s;
    }
    // b2' = W2@b1 + b2
    if (tid < 84) {
        float s = b2[tid];
        const float* r = sW2 + tid * 120;
        for (int k = 0; k < 120; k++) s = fmaf(r[k], b1[k], s);
        sb2p[tid] = s;
    }
    __syncthreads();

    if (q == 0 && tid < 10) {
        float s = b3[tid];
        const float* r = W3 + tid * 84;
        for (int m = 0; m < 84; m++) s = fmaf(r[m], sb2p[m], s);
        g_b3[chain * 10 + tid] = s;
    }

    // T2[o][j] = sum_k S[o][k] * W1[k][j], j in this quarter (100 cols)
    if (tid < 100) {
        int j = q * 100 + tid;
        float acc[10];
#pragma unroll
        for (int o = 0; o < 10; o++) acc[o] = 0.f;
        for (int k = 0; k < 120; k++) {
            float w1v = W1[k * 400 + j];
#pragma unroll
            for (int o = 0; o < 10; o++) acc[o] = fmaf(sS[o * 120 + k], w1v, acc[o]);
        }
#pragma unroll
        for (int o = 0; o < 10; o++) g_T2[(chain * 10 + o) * 400 + j] = acc[o];
    }
}

// ---------------------------------------------------------------------------
// Main fused kernel: one block (192 threads) per image. occupancy target 4.
// ---------------------------------------------------------------------------
__global__ void __launch_bounds__(192, 4)
k_main(const float* __restrict__ x,
       const float* __restrict__ c1w, const float* __restrict__ c1b,
       const float* __restrict__ c2w, const float* __restrict__ c2b,
       const float* __restrict__ sw4, const float* __restrict__ sb4,
       float* __restrict__ out) {
    __shared__ __align__(16) float  s_x[3 * 32 * 36];   // padded rows; aliased s_part later
    __shared__ __align__(16) float  s_y1[6 * 14 * 20];  // pool1 out, padded rows
    __shared__ __align__(16) float2 s_w1p[450];         // {w,w} pairs
    __shared__ __align__(16) float2 s_w2p[2400];
    __shared__ float s_b1[6], s_b2[16];
    __shared__ __align__(16) float s_xf[400];
    __shared__ float hs[10], shp[4];

    int b = blockIdx.x, tid = threadIdx.x;

    // ---- load phase ----
    const float4* xg = (const float4*)(x + b * 3072);
    for (int g = tid; g < 768; g += 192) {
        float4 v = xg[g];
        int gr = g >> 3, c4 = g & 7;
        *(float4*)(s_x + gr * 36 + c4 * 4) = v;
    }
    for (int i = tid; i < 450; i += 192)  { float w = c1w[i]; s_w1p[i] = make_float2(w, w); }
    for (int i = tid; i < 2400; i += 192) { float w = c2w[i]; s_w2p[i] = make_float2(w, w); }
    if (tid < 6)  s_b1[tid] = c1b[tid];
    if (tid < 16) s_b2[tid] = c2b[tid];
    __syncthreads();

    // ---- conv1 + relu + pool: task = (ch, pooled row, half) = 168 tasks ----
    if (tid < 168) {
        int ch = tid / 28, rem = tid % 28, py = rem >> 1, h = rem & 1;
        u64 acc0[7], acc1[7];
#pragma unroll
        for (int j = 0; j < 7; j++) { acc0[j] = 0ull; acc1[j] = 0ull; }
        const float* xbase = s_x + (2 * py) * 36 + 14 * h;
#pragma unroll 1
        for (int ic = 0; ic < 3; ic++) {
            const float2* wb = s_w1p + (ch * 3 + ic) * 25;
#pragma unroll
            for (int xr = 0; xr < 6; xr++) {
                const u64* rp = (const u64*)(xbase + ic * (32 * 36) + xr * 36);
                u64 pe[9]; float xl[9], xh[9];
#pragma unroll
                for (int m = 0; m < 9; m++) { pe[m] = rp[m]; upk(pe[m], xl[m], xh[m]); }
                u64 po[8];
#pragma unroll
                for (int m = 0; m < 8; m++) po[m] = pk(xh[m], xl[m + 1]);
                if (xr < 5) {
#pragma unroll
                    for (int kx = 0; kx < 5; kx++) {
                        u64 w = *(const u64*)&wb[xr * 5 + kx];
#pragma unroll
                        for (int j = 0; j < 7; j++)
                            acc0[j] = fma2(w, (kx & 1) ? po[j + (kx >> 1)] : pe[j + (kx >> 1)], acc0[j]);
                    }
                }
                if (xr >= 1) {
#pragma unroll
                    for (int kx = 0; kx < 5; kx++) {
                        u64 w = *(const u64*)&wb[(xr - 1) * 5 + kx];
#pragma unroll
                        for (int j = 0; j < 7; j++)
                            acc1[j] = fma2(w, (kx & 1) ? po[j + (kx >> 1)] : pe[j + (kx >> 1)], acc1[j]);
                    }
                }
            }
        }
        float bv = s_b1[ch];
        float* yrow = s_y1 + (ch * 14 + py) * 20 + 7 * h;
#pragma unroll
        for (int j = 0; j < 7; j++) {
            float a0, a1, c0, c1;
            upk(acc0[j], a0, a1); upk(acc1[j], c0, c1);
            float m = fmaxf(fmaxf(a0, a1), fmaxf(c0, c1)) + bv;
            yrow[j] = fmaxf(m, 0.f);
        }
    }
    __syncthreads();

    // ---- conv2: task = (icg, ch, pooled row) = 160 tasks, 2-way K split ----
    float* s_part = s_x;  // alias: x is dead
    int icg = tid / 80;
    int r2 = tid % 80, ch2 = r2 / 5, py2 = r2 % 5;
    u64 b0[5], b1[5];
    if (tid < 160) {
#pragma unroll
        for (int j = 0; j < 5; j++) { b0[j] = 0ull; b1[j] = 0ull; }
#pragma unroll 1
        for (int ici = 0; ici < 3; ici++) {
            int ic = icg * 3 + ici;
            const float2* wb = s_w2p + (ch2 * 6 + ic) * 25;
#pragma unroll
            for (int xr = 0; xr < 6; xr++) {
                const u64* rp = (const u64*)(s_y1 + (ic * 14 + 2 * py2 + xr) * 20);
                u64 pe[7]; float xl[7], xh[7];
#pragma unroll
                for (int m = 0; m < 7; m++) { pe[m] = rp[m]; upk(pe[m], xl[m], xh[m]); }
                u64 po[6];
#pragma unroll
                for (int m = 0; m < 6; m++) po[m] = pk(xh[m], xl[m + 1]);
                if (xr < 5) {
#pragma unroll
                    for (int kx = 0; kx < 5; kx++) {
                        u64 w = *(const u64*)&wb[xr * 5 + kx];
#pragma unroll
                        for (int j = 0; j < 5; j++)
                            b0[j] = fma2(w, (kx & 1) ? po[j + (kx >> 1)] : pe[j + (kx >> 1)], b0[j]);
                    }
                }
                if (xr >= 1) {
#pragma unroll
                    for (int kx = 0; kx < 5; kx++) {
                        u64 w = *(const u64*)&wb[(xr - 1) * 5 + kx];
#pragma unroll
                        for (int j = 0; j < 5; j++)
                            b1[j] = fma2(w, (kx & 1) ? po[j + (kx >> 1)] : pe[j + (kx >> 1)], b1[j]);
                    }
                }
            }
        }
        if (icg == 1) {
            float* pp = s_part + r2 * 20;
#pragma unroll
            for (int j = 0; j < 5; j++) {
                float a, bq;
                upk(b0[j], a, bq); pp[2 * j] = a; pp[2 * j + 1] = bq;
                upk(b1[j], a, bq); pp[10 + 2 * j] = a; pp[10 + 2 * j + 1] = bq;
            }
        }
    }
    __syncthreads();

    // combine halves + pool + relu -> xf
    if (tid < 80) {
        float bv = s_b2[ch2];
        const float* pp = s_part + r2 * 20;
        float* xfp = s_xf + ch2 * 25 + py2 * 5;
        float* gxf = g_xf + (size_t)b * 400 + ch2 * 25 + py2 * 5;
#pragma unroll
        for (int j = 0; j < 5; j++) {
            float a0, a1, c0, c1;
            upk(b0[j], a0, a1); upk(b1[j], c0, c1);
            float v = fmaxf(fmaxf(a0 + pp[2 * j], a1 + pp[2 * j + 1]),
                            fmaxf(c0 + pp[10 + 2 * j], c1 + pp[10 + 2 * j + 1])) + bv;
            v = fmaxf(v, 0.f);
            xfp[j] = v; gxf[j] = v;
        }
    }
    __syncthreads();

    // ---- h = Ws @ xf + bs (10 outputs x 16 lanes) ----
    if (tid < 160) {
        int o = tid >> 4, l = tid & 15;
        const float* wr = g_T2 + o * 400;
        float s = 0.f;
        for (int j = l; j < 400; j += 16) s = fmaf(wr[j], s_xf[j], s);
        s += __shfl_down_sync(0xffffffffu, s, 8, 16);
        s += __shfl_down_sync(0xffffffffu, s, 4, 16);
        s += __shfl_down_sync(0xffffffffu, s, 2, 16);
        s += __shfl_down_sync(0xffffffffu, s, 1, 16);
        if (l == 0) hs[o] = s + g_b3[o];
    }
    __syncthreads();

    // shapes = relu(h) @ sw4.T + sb4
    if (tid < 4) {
        float s = sb4[tid];
#pragma unroll
        for (int o = 0; o < 10; o++)
            s = fmaf(fmaxf(hs[o], 0.f), sw4[tid * 10 + o], s);
        shp[tid] = s;
        out[b * 4 + tid] = s;
    }
    __syncthreads();

    // routing: argmax (first-max tiebreak), slot-spread atomicMax of (b<<2)|pred
    if (tid == 0) {
        int pred = 0;
        float best = shp[0];
#pragma unroll
        for (int k = 1; k < 4; k++)
            if (shp[k] > best) { best = shp[k]; pred = k; }
        const int widths[4] = {3, 5, 6, 5};
        int w = widths[pred];
        int val = (b << 2) | pred;
        int slot = b & 31;
        for (int c = 0; c < w; c++) atomicMax(&g_last[c * 32 + slot], val);
    }
}

// ---------------------------------------------------------------------------
// out[b][c] = covered(c) ? dot(xf[b], We_row) + be : 0
// We_row computed inline: We[e][c][j] = sum_k ew4[e][c][k] * T2[1+e][k][j]
// ---------------------------------------------------------------------------
__global__ void __launch_bounds__(256)
k_out(const float* __restrict__ ew4, const float* __restrict__ eb4,
      float* __restrict__ out) {
    __shared__ float wsel[6 * 400];
    __shared__ float bsel[6];
    __shared__ int   psel[6];
    __shared__ float sw4e[240];
    int tid = threadIdx.x;
    if (tid < 240) sw4e[tid] = ew4[tid];
    if (tid < 6) {
        int mx = -1;
#pragma unroll
        for (int s = 0; s < 32; s++) mx = max(mx, g_last[tid * 32 + s]);
        psel[tid] = mx;
    }
    __syncthreads();
    for (int idx = tid; idx < 2400; idx += 256) {
        int c = idx / 400, j = idx - c * 400;
        int p = psel[c];
        float s = 0.f;
        if (p >= 0) {
            int e = p & 3;
            const float* w4r = sw4e + e * 60 + c * 10;
            const float* t2 = g_T2 + (1 + e) * 10 * 400 + j;
#pragma unroll
            for (int k = 0; k < 10; k++) s = fmaf(w4r[k], t2[k * 400], s);
        }
        wsel[idx] = s;
    }
    if (tid < 6) {
        int p = psel[tid];
        float s = 0.f;
        if (p >= 0) {
            int e = p & 3;
            s = eb4[e * 6 + tid];
#pragma unroll
            for (int k = 0; k < 10; k++)
                s = fmaf(sw4e[e * 60 + tid * 10 + k], g_b3[(1 + e) * 10 + k], s);
        }
        bsel[tid] = s;
    }
    __syncthreads();
    int c = tid & 7, r = tid >> 3;
    int b = blockIdx.x * 32 + r;
    if (c < 6) {
        const float* xfp = g_xf + (size_t)b * 400;
        const float* wr = wsel + c * 400;
        float s = bsel[c];
        for (int j = 0; j < 400; j++) s = fmaf(xfp[j], wr[j], s);
        out[B_TOTAL * 4 + b * 6 + c] = s;
    }
}

// ---------------------------------------------------------------------------
extern "C" void kernel_launch(void* const* d_in, const int* in_sizes, int n_in,
                              void* d_out, int out_size) {
    const float* x    = (const float*)d_in[0];
    const float* c1w  = (const float*)d_in[1];
    const float* c1b  = (const float*)d_in[2];
    const float* c2w  = (const float*)d_in[3];
    const float* c2b  = (const float*)d_in[4];
    const float* sw1  = (const float*)d_in[5];
    const float* sb1  = (const float*)d_in[6];
    const float* sw2  = (const float*)d_in[7];
    const float* sb2  = (const float*)d_in[8];
    const float* sw3  = (const float*)d_in[9];
    const float* sb3  = (const float*)d_in[10];
    const float* sw4  = (const float*)d_in[11];
    const float* sb4  = (const float*)d_in[12];
    const float* ew1  = (const float*)d_in[13];
    const float* eb1  = (const float*)d_in[14];
    const float* ew2  = (const float*)d_in[15];
    const float* eb2  = (const float*)d_in[16];
    const float* ew3  = (const float*)d_in[17];
    const float* eb3  = (const float*)d_in[18];
    const float* ew4  = (const float*)d_in[19];
    const float* eb4  = (const float*)d_in[20];
    float* out = (float*)d_out;

    kc_prep<<<20, 256>>>(sw1, sb1, sw2, sb2, sw3, sb3,
                         ew1, eb1, ew2, eb2, ew3, eb3);
    k_main<<<B_TOTAL, 192>>>(x, c1w, c1b, c2w, c2b, sw4, sb4, out);
    k_out<<<B_TOTAL / 32, 256>>>(ew4, eb4, out);
}

// round 4
// speedup vs baseline: 1.5845x; 1.5845x over previous
#include <cuda_runtime.h>
#include <cuda_bf16.h>

// ---------------------------------------------------------------------------
// RtoVMainModel: conv1(3->6,5x5)+relu+pool2 ; conv2(6->16,5x5)+relu+pool2 ;
// flatten(400) ; linear chains collapsed at runtime: S=W3@W2, T2=S@W1.
// Experts' final selected rows built in k_out from ew4 x T2.
// d_out layout: [shapes (B*4) | out (B*6)] float32
// ---------------------------------------------------------------------------

#define B_TOTAL 16384
typedef unsigned long long u64;

__device__ __forceinline__ u64 pk(float lo, float hi) {
    u64 r; asm("mov.b64 %0, {%1, %2};" : "=l"(r) : "f"(lo), "f"(hi)); return r;
}
__device__ __forceinline__ void upk(u64 p, float& lo, float& hi) {
    asm("mov.b64 {%0, %1}, %2;" : "=f"(lo), "=f"(hi) : "l"(p));
}
__device__ __forceinline__ u64 fma2(u64 a, u64 b, u64 c) {
    u64 d; asm("fma.rn.f32x2 %0, %1, %2, %3;" : "=l"(d) : "l"(a), "l"(b), "l"(c)); return d;
}

// scratch (device globals: no allocation allowed)
__device__ float g_T2[5 * 10 * 400];   // chain 0 = shapes head collapsed (10x400)
__device__ float g_b3[5 * 10];         // collapsed bias through layer 3
__device__ float g_xf[B_TOTAL * 400];  // flattened conv features
__device__ int   g_last[6 * 32];       // routing slots: [col][b&31]

// ---------------------------------------------------------------------------
// Prologue: grid = 5 chains x 16 column-chunks = 80 blocks, 256 threads.
// Each block: load W2 + its 25-col W1 slice to smem; S = W3@W2 (redundant,
// cheap); T2 slice = S @ W1_slice; chunk 0 also does the bias chain.
// ---------------------------------------------------------------------------
__global__ void __launch_bounds__(256)
kc_prep(const float* __restrict__ sw1, const float* __restrict__ sb1,
        const float* __restrict__ sw2, const float* __restrict__ sb2,
        const float* __restrict__ sw3, const float* __restrict__ sb3,
        const float* __restrict__ ew1, const float* __restrict__ eb1,
        const float* __restrict__ ew2, const float* __restrict__ eb2,
        const float* __restrict__ ew3, const float* __restrict__ eb3) {
    __shared__ float sW2[84 * 120];
    __shared__ float sW1c[120 * 25];
    __shared__ float sS[10 * 120];
    __shared__ float sb2p[84];

    int chain = blockIdx.x >> 4, chunk = blockIdx.x & 15;
    int j0 = chunk * 25;
    int tid = threadIdx.x;
    if (blockIdx.x == 0 && tid < 192) g_last[tid] = -1;

    const float* W1 = chain ? (ew1 + (chain - 1) * 120 * 400) : sw1;
    const float* W2 = chain ? (ew2 + (chain - 1) * 84 * 120) : sw2;
    const float* W3 = chain ? (ew3 + (chain - 1) * 10 * 84) : sw3;
    const float* b1 = chain ? (eb1 + (chain - 1) * 120) : sb1;
    const float* b2 = chain ? (eb2 + (chain - 1) * 84) : sb2;
    const float* b3 = chain ? (eb3 + (chain - 1) * 10) : sb3;

    for (int i = tid; i < 10080; i += 256) sW2[i] = W2[i];
    for (int i = tid; i < 3000; i += 256) {
        int row = i / 25, col = i - row * 25;
        sW1c[i] = W1[row * 400 + j0 + col];
    }
    __syncthreads();

    // S[o][k] = sum_m W3[o][m] * W2[m][k]
    for (int p = tid; p < 1200; p += 256) {
        int o = p / 120, k = p - o * 120;
        float s = 0.f;
        const float* w3r = W3 + o * 84;
        for (int m = 0; m < 84; m++) s = fmaf(w3r[m], sW2[m * 120 + k], s);
        sS[p] = s;
    }
    // b2' = W2@b1 + b2
    if (tid < 84) {
        float s = b2[tid];
        const float* r = sW2 + tid * 120;
        for (int k = 0; k < 120; k++) s = fmaf(r[k], b1[k], s);
        sb2p[tid] = s;
    }
    __syncthreads();

    if (chunk == 0 && tid < 10) {
        float s = b3[tid];
        const float* r = W3 + tid * 84;
        for (int m = 0; m < 84; m++) s = fmaf(r[m], sb2p[m], s);
        g_b3[chain * 10 + tid] = s;
    }

    // T2[o][j0+jj] = sum_k S[o][k] * W1[k][j0+jj]
    if (tid < 250) {
        int o = tid / 25, jj = tid - o * 25;
        float s = 0.f;
        const float* sr = sS + o * 120;
        for (int k = 0; k < 120; k++) s = fmaf(sr[k], sW1c[k * 25 + jj], s);
        g_T2[(chain * 10 + o) * 400 + j0 + jj] = s;
    }
}

// ---------------------------------------------------------------------------
// Main fused kernel: one block (192 threads) per image. (R1 structure:
// launch_bounds(192,3) so the ~110 live regs do NOT spill.)
// ---------------------------------------------------------------------------
__global__ void __launch_bounds__(192, 3)
k_main(const float* __restrict__ x,
       const float* __restrict__ c1w, const float* __restrict__ c1b,
       const float* __restrict__ c2w, const float* __restrict__ c2b,
       const float* __restrict__ sw4, const float* __restrict__ sb4,
       float* __restrict__ out) {
    __shared__ __align__(16) float  s_x[3 * 32 * 36];   // padded rows; aliased s_part later
    __shared__ __align__(16) float  s_y1[6 * 14 * 20];  // pool1 out, padded rows
    __shared__ __align__(16) float2 s_w1p[450];         // {w,w} pairs
    __shared__ __align__(16) float2 s_w2p[2400];
    __shared__ float s_b1[6], s_b2[16];
    __shared__ __align__(16) float s_xf[400];
    __shared__ float hs[10], shp[4];

    int b = blockIdx.x, tid = threadIdx.x;

    // ---- load phase ----
    const float4* xg = (const float4*)(x + b * 3072);
    for (int g = tid; g < 768; g += 192) {
        float4 v = xg[g];
        int gr = g >> 3, c4 = g & 7;
        *(float4*)(s_x + gr * 36 + c4 * 4) = v;
    }
    for (int i = tid; i < 450; i += 192)  { float w = c1w[i]; s_w1p[i] = make_float2(w, w); }
    for (int i = tid; i < 2400; i += 192) { float w = c2w[i]; s_w2p[i] = make_float2(w, w); }
    if (tid < 6)  s_b1[tid] = c1b[tid];
    if (tid < 16) s_b2[tid] = c2b[tid];
    __syncthreads();

    // ---- conv1 + relu + pool: task = (ch, pooled row, half) = 168 tasks ----
    if (tid < 168) {
        int ch = tid / 28, rem = tid % 28, py = rem >> 1, h = rem & 1;
        u64 acc0[7], acc1[7];
#pragma unroll
        for (int j = 0; j < 7; j++) { acc0[j] = 0ull; acc1[j] = 0ull; }
        const float* xbase = s_x + (2 * py) * 36 + 14 * h;
#pragma unroll 1
        for (int ic = 0; ic < 3; ic++) {
            const float2* wb = s_w1p + (ch * 3 + ic) * 25;
            u64 wv[5][5];
#pragma unroll
            for (int xr = 0; xr < 6; xr++) {
                const u64* rp = (const u64*)(xbase + ic * (32 * 36) + xr * 36);
                u64 pe[9]; float xl[9], xh[9];
#pragma unroll
                for (int m = 0; m < 9; m++) { pe[m] = rp[m]; upk(pe[m], xl[m], xh[m]); }
                u64 po[8];
#pragma unroll
                for (int m = 0; m < 8; m++) po[m] = pk(xh[m], xl[m + 1]);
                if (xr < 5) {
#pragma unroll
                    for (int k = 0; k < 5; k++) wv[xr][k] = *(const u64*)&wb[xr * 5 + k];
#pragma unroll
                    for (int kx = 0; kx < 5; kx++) {
                        u64 w = wv[xr][kx];
#pragma unroll
                        for (int j = 0; j < 7; j++)
                            acc0[j] = fma2(w, (kx & 1) ? po[j + (kx >> 1)] : pe[j + (kx >> 1)], acc0[j]);
                    }
                }
                if (xr >= 1) {
#pragma unroll
                    for (int kx = 0; kx < 5; kx++) {
                        u64 w = wv[xr - 1][kx];
#pragma unroll
                        for (int j = 0; j < 7; j++)
                            acc1[j] = fma2(w, (kx & 1) ? po[j + (kx >> 1)] : pe[j + (kx >> 1)], acc1[j]);
                    }
                }
            }
        }
        float bv = s_b1[ch];
        float* yrow = s_y1 + (ch * 14 + py) * 20 + 7 * h;
#pragma unroll
        for (int j = 0; j < 7; j++) {
            float a0, a1, c0, c1;
            upk(acc0[j], a0, a1); upk(acc1[j], c0, c1);
            float m = fmaxf(fmaxf(a0, a1), fmaxf(c0, c1)) + bv;
            yrow[j] = fmaxf(m, 0.f);
        }
    }
    __syncthreads();

    // ---- conv2: task = (icg, ch, pooled row) = 160 tasks, 2-way K split ----
    float* s_part = s_x;  // alias: x is dead
    int icg = tid / 80;
    int r2 = tid % 80, ch2 = r2 / 5, py2 = r2 % 5;
    u64 b0[5], b1[5];
    if (tid < 160) {
#pragma unroll
        for (int j = 0; j < 5; j++) { b0[j] = 0ull; b1[j] = 0ull; }
#pragma unroll 1
        for (int ici = 0; ici < 3; ici++) {
            int ic = icg * 3 + ici;
            const float2* wb = s_w2p + (ch2 * 6 + ic) * 25;
            u64 wv[5][5];
#pragma unroll
            for (int xr = 0; xr < 6; xr++) {
                const u64* rp = (const u64*)(s_y1 + (ic * 14 + 2 * py2 + xr) * 20);
                u64 pe[7]; float xl[7], xh[7];
#pragma unroll
                for (int m = 0; m < 7; m++) { pe[m] = rp[m]; upk(pe[m], xl[m], xh[m]); }
                u64 po[6];
#pragma unroll
                for (int m = 0; m < 6; m++) po[m] = pk(xh[m], xl[m + 1]);
                if (xr < 5) {
#pragma unroll
                    for (int k = 0; k < 5; k++) wv[xr][k] = *(const u64*)&wb[xr * 5 + k];
#pragma unroll
                    for (int kx = 0; kx < 5; kx++) {
                        u64 w = wv[xr][kx];
#pragma unroll
                        for (int j = 0; j < 5; j++)
                            b0[j] = fma2(w, (kx & 1) ? po[j + (kx >> 1)] : pe[j + (kx >> 1)], b0[j]);
                    }
                }
                if (xr >= 1) {
#pragma unroll
                    for (int kx = 0; kx < 5; kx++) {
                        u64 w = wv[xr - 1][kx];
#pragma unroll
                        for (int j = 0; j < 5; j++)
                            b1[j] = fma2(w, (kx & 1) ? po[j + (kx >> 1)] : pe[j + (kx >> 1)], b1[j]);
                    }
                }
            }
        }
        if (icg == 1) {
            float* pp = s_part + r2 * 20;
#pragma unroll
            for (int j = 0; j < 5; j++) {
                float a, bq;
                upk(b0[j], a, bq); pp[2 * j] = a; pp[2 * j + 1] = bq;
                upk(b1[j], a, bq); pp[10 + 2 * j] = a; pp[10 + 2 * j + 1] = bq;
            }
        }
    }
    __syncthreads();

    // combine halves + pool + relu -> xf
    if (tid < 80) {
        float bv = s_b2[ch2];
        const float* pp = s_part + r2 * 20;
        float* xfp = s_xf + ch2 * 25 + py2 * 5;
        float* gxf = g_xf + (size_t)b * 400 + ch2 * 25 + py2 * 5;
#pragma unroll
        for (int j = 0; j < 5; j++) {
            float a0, a1, c0, c1;
            upk(b0[j], a0, a1); upk(b1[j], c0, c1);
            float v = fmaxf(fmaxf(a0 + pp[2 * j], a1 + pp[2 * j + 1]),
                            fmaxf(c0 + pp[10 + 2 * j], c1 + pp[10 + 2 * j + 1])) + bv;
            v = fmaxf(v, 0.f);
            xfp[j] = v; gxf[j] = v;
        }
    }
    __syncthreads();

    // ---- h = Ws @ xf + bs (10 outputs x 16 lanes) ----
    if (tid < 160) {
        int o = tid >> 4, l = tid & 15;
        const float* wr = g_T2 + o * 400;
        float s = 0.f;
        for (int j = l; j < 400; j += 16) s = fmaf(wr[j], s_xf[j], s);
        s += __shfl_down_sync(0xffffffffu, s, 8, 16);
        s += __shfl_down_sync(0xffffffffu, s, 4, 16);
        s += __shfl_down_sync(0xffffffffu, s, 2, 16);
        s += __shfl_down_sync(0xffffffffu, s, 1, 16);
        if (l == 0) hs[o] = s + g_b3[o];
    }
    __syncthreads();

    // shapes = relu(h) @ sw4.T + sb4
    if (tid < 4) {
        float s = sb4[tid];
#pragma unroll
        for (int o = 0; o < 10; o++)
            s = fmaf(fmaxf(hs[o], 0.f), sw4[tid * 10 + o], s);
        shp[tid] = s;
        out[b * 4 + tid] = s;
    }
    __syncthreads();

    // routing: argmax (first-max tiebreak), slot-spread atomicMax of (b<<2)|pred
    if (tid == 0) {
        int pred = 0;
        float best = shp[0];
#pragma unroll
        for (int k = 1; k < 4; k++)
            if (shp[k] > best) { best = shp[k]; pred = k; }
        const int widths[4] = {3, 5, 6, 5};
        int w = widths[pred];
        int val = (b << 2) | pred;
        int slot = b & 31;
        for (int c = 0; c < w; c++) atomicMax(&g_last[c * 32 + slot], val);
    }
}

// ---------------------------------------------------------------------------
// out[b][c] = covered(c) ? dot(xf[b], We_row) + be : 0
// We_row computed inline: We[e][c][j] = sum_k ew4[e][c][k] * T2[1+e][k][j]
// ---------------------------------------------------------------------------
__global__ void __launch_bounds__(256)
k_out(const float* __restrict__ ew4, const float* __restrict__ eb4,
      float* __restrict__ out) {
    __shared__ float wsel[6 * 400];
    __shared__ float bsel[6];
    __shared__ int   psel[6];
    __shared__ float sw4e[240];
    int tid = threadIdx.x;
    if (tid < 240) sw4e[tid] = ew4[tid];
    if (tid < 6) {
        int mx = -1;
#pragma unroll
        for (int s = 0; s < 32; s++) mx = max(mx, g_last[tid * 32 + s]);
        psel[tid] = mx;
    }
    __syncthreads();
    for (int idx = tid; idx < 2400; idx += 256) {
        int c = idx / 400, j = idx - c * 400;
        int p = psel[c];
        float s = 0.f;
        if (p >= 0) {
            int e = p & 3;
            const float* w4r = sw4e + e * 60 + c * 10;
            const float* t2 = g_T2 + (1 + e) * 10 * 400 + j;
#pragma unroll
            for (int k = 0; k < 10; k++) s = fmaf(w4r[k], t2[k * 400], s);
        }
        wsel[idx] = s;
    }
    if (tid < 6) {
        int p = psel[tid];
        float s = 0.f;
        if (p >= 0) {
            int e = p & 3;
            s = eb4[e * 6 + tid];
#pragma unroll
            for (int k = 0; k < 10; k++)
                s = fmaf(sw4e[e * 60 + tid * 10 + k], g_b3[(1 + e) * 10 + k], s);
        }
        bsel[tid] = s;
    }
    __syncthreads();
    int c = tid & 7, r = tid >> 3;
    int b = blockIdx.x * 32 + r;
    if (c < 6) {
        const float* xfp = g_xf + (size_t)b * 400;
        const float* wr = wsel + c * 400;
        float s = bsel[c];
        for (int j = 0; j < 400; j++) s = fmaf(xfp[j], wr[j], s);
        out[B_TOTAL * 4 + b * 6 + c] = s;
    }
}

// ---------------------------------------------------------------------------
extern "C" void kernel_launch(void* const* d_in, const int* in_sizes, int n_in,
                              void* d_out, int out_size) {
    const float* x    = (const float*)d_in[0];
    const float* c1w  = (const float*)d_in[1];
    const float* c1b  = (const float*)d_in[2];
    const float* c2w  = (const float*)d_in[3];
    const float* c2b  = (const float*)d_in[4];
    const float* sw1  = (const float*)d_in[5];
    const float* sb1  = (const float*)d_in[6];
    const float* sw2  = (const float*)d_in[7];
    const float* sb2  = (const float*)d_in[8];
    const float* sw3  = (const float*)d_in[9];
    const float* sb3  = (const float*)d_in[10];
    const float* sw4  = (const float*)d_in[11];
    const float* sb4  = (const float*)d_in[12];
    const float* ew1  = (const float*)d_in[13];
    const float* eb1  = (const float*)d_in[14];
    const float* ew2  = (const float*)d_in[15];
    const float* eb2  = (const float*)d_in[16];
    const float* ew3  = (const float*)d_in[17];
    const float* eb3  = (const float*)d_in[18];
    const float* ew4  = (const float*)d_in[19];
    const float* eb4  = (const float*)d_in[20];
    float* out = (float*)d_out;

    kc_prep<<<80, 256>>>(sw1, sb1, sw2, sb2, sw3, sb3,
                         ew1, eb1, ew2, eb2, ew3, eb3);
    k_main<<<B_TOTAL, 192>>>(x, c1w, c1b, c2w, c2b, sw4, sb4, out);
    k_out<<<B_TOTAL / 32, 256>>>(ew4, eb4, out);
}

// round 5
// speedup vs baseline: 1.6224x; 1.0239x over previous
#include <cuda_runtime.h>
#include <cuda_bf16.h>

// ---------------------------------------------------------------------------
// RtoVMainModel. conv chains per image in smem; linear heads collapsed at
// runtime (S=W3@W2, T2=S@W1). 2 images per k_main block.
// d_out layout: [shapes (B*4) | out (B*6)] float32
// ---------------------------------------------------------------------------

#define B_TOTAL 16384
typedef unsigned long long u64;

__device__ __forceinline__ u64 pk(float lo, float hi) {
    u64 r; asm("mov.b64 %0, {%1, %2};" : "=l"(r) : "f"(lo), "f"(hi)); return r;
}
__device__ __forceinline__ void upk(u64 p, float& lo, float& hi) {
    asm("mov.b64 {%0, %1}, %2;" : "=f"(lo), "=f"(hi) : "l"(p));
}
__device__ __forceinline__ u64 fma2(u64 a, u64 b, u64 c) {
    u64 d; asm("fma.rn.f32x2 %0, %1, %2, %3;" : "=l"(d) : "l"(a), "l"(b), "l"(c)); return d;
}

// scratch (device globals: no allocation allowed)
__device__ float g_T2[5 * 10 * 400];
__device__ float g_b3[5 * 10];
__device__ float g_xf[B_TOTAL * 400];
__device__ int   g_last[6 * 32];

// ---------------------------------------------------------------------------
// Prologue: grid = 5 chains x 16 column-chunks = 80 blocks, 256 threads.
// ---------------------------------------------------------------------------
__global__ void __launch_bounds__(256)
kc_prep(const float* __restrict__ sw1, const float* __restrict__ sb1,
        const float* __restrict__ sw2, const float* __restrict__ sb2,
        const float* __restrict__ sw3, const float* __restrict__ sb3,
        const float* __restrict__ ew1, const float* __restrict__ eb1,
        const float* __restrict__ ew2, const float* __restrict__ eb2,
        const float* __restrict__ ew3, const float* __restrict__ eb3) {
    __shared__ float sW2[84 * 120];
    __shared__ float sW1c[120 * 25];
    __shared__ float sS[10 * 120];
    __shared__ float sb2p[84];

    int chain = blockIdx.x >> 4, chunk = blockIdx.x & 15;
    int j0 = chunk * 25;
    int tid = threadIdx.x;
    if (blockIdx.x == 0 && tid < 192) g_last[tid] = -1;

    const float* W1 = chain ? (ew1 + (chain - 1) * 120 * 400) : sw1;
    const float* W2 = chain ? (ew2 + (chain - 1) * 84 * 120) : sw2;
    const float* W3 = chain ? (ew3 + (chain - 1) * 10 * 84) : sw3;
    const float* b1 = chain ? (eb1 + (chain - 1) * 120) : sb1;
    const float* b2 = chain ? (eb2 + (chain - 1) * 84) : sb2;
    const float* b3 = chain ? (eb3 + (chain - 1) * 10) : sb3;

    for (int i = tid; i < 10080; i += 256) sW2[i] = W2[i];
    for (int i = tid; i < 3000; i += 256) {
        int row = i / 25, col = i - row * 25;
        sW1c[i] = W1[row * 400 + j0 + col];
    }
    __syncthreads();

    for (int p = tid; p < 1200; p += 256) {
        int o = p / 120, k = p - o * 120;
        float s = 0.f;
        const float* w3r = W3 + o * 84;
        for (int m = 0; m < 84; m++) s = fmaf(w3r[m], sW2[m * 120 + k], s);
        sS[p] = s;
    }
    if (tid < 84) {
        float s = b2[tid];
        const float* r = sW2 + tid * 120;
        for (int k = 0; k < 120; k++) s = fmaf(r[k], b1[k], s);
        sb2p[tid] = s;
    }
    __syncthreads();

    if (chunk == 0 && tid < 10) {
        float s = b3[tid];
        const float* r = W3 + tid * 84;
        for (int m = 0; m < 84; m++) s = fmaf(r[m], sb2p[m], s);
        g_b3[chain * 10 + tid] = s;
    }

    if (tid < 250) {
        int o = tid / 25, jj = tid - o * 25;
        float s = 0.f;
        const float* sr = sS + o * 120;
        for (int k = 0; k < 120; k++) s = fmaf(sr[k], sW1c[k * 25 + jj], s);
        g_T2[(chain * 10 + o) * 400 + j0 + jj] = s;
    }
}

// ---------------------------------------------------------------------------
// Main fused kernel: one block (192 threads) per TWO images.
// ---------------------------------------------------------------------------
__global__ void __launch_bounds__(192, 3)
k_main(const float* __restrict__ x,
       const float* __restrict__ c1w, const float* __restrict__ c1b,
       const float* __restrict__ c2w, const float* __restrict__ c2b,
       const float* __restrict__ sw4, const float* __restrict__ sb4,
       float* __restrict__ out) {
    __shared__ __align__(16) float  s_x[3 * 32 * 36];    // reused per image
    __shared__ __align__(16) float  s_y1[2][6 * 14 * 20];
    __shared__ __align__(16) float2 s_w1p[450];
    __shared__ __align__(16) float2 s_w2p[2400];
    __shared__ float s_b1[6], s_b2[16];
    __shared__ __align__(16) float s_xf[2][400];
    __shared__ float hs[2][10], shp[2][4];

    int b0i = blockIdx.x * 2, tid = threadIdx.x;

    // ---- load weights + image 0 ----
    {
        const float4* xg = (const float4*)(x + (size_t)b0i * 3072);
        for (int g = tid; g < 768; g += 192) {
            float4 v = xg[g];
            int gr = g >> 3, c4 = g & 7;
            *(float4*)(s_x + gr * 36 + c4 * 4) = v;
        }
    }
    for (int i = tid; i < 450; i += 192)  { float w = c1w[i]; s_w1p[i] = make_float2(w, w); }
    for (int i = tid; i < 2400; i += 192) { float w = c2w[i]; s_w2p[i] = make_float2(w, w); }
    if (tid < 6)  s_b1[tid] = c1b[tid];
    if (tid < 16) s_b2[tid] = c2b[tid];
    __syncthreads();

    // ---- conv1 for img 0, then reload x, conv1 for img 1 ----
#pragma unroll 1
    for (int img = 0; img < 2; img++) {
        if (tid < 168) {
            int ch = tid / 28, rem = tid % 28, py = rem >> 1, h = rem & 1;
            u64 acc0[7], acc1[7];
#pragma unroll
            for (int j = 0; j < 7; j++) { acc0[j] = 0ull; acc1[j] = 0ull; }
            const float* xbase = s_x + (2 * py) * 36 + 14 * h;
#pragma unroll 1
            for (int ic = 0; ic < 3; ic++) {
                const float2* wb = s_w1p + (ch * 3 + ic) * 25;
                u64 wv[5][5];
#pragma unroll
                for (int xr = 0; xr < 6; xr++) {
                    const u64* rp = (const u64*)(xbase + ic * (32 * 36) + xr * 36);
                    u64 pe[9]; float xl[9], xh[9];
#pragma unroll
                    for (int m = 0; m < 9; m++) { pe[m] = rp[m]; upk(pe[m], xl[m], xh[m]); }
                    u64 po[8];
#pragma unroll
                    for (int m = 0; m < 8; m++) po[m] = pk(xh[m], xl[m + 1]);
                    if (xr < 5) {
#pragma unroll
                        for (int k = 0; k < 5; k++) wv[xr][k] = *(const u64*)&wb[xr * 5 + k];
#pragma unroll
                        for (int kx = 0; kx < 5; kx++) {
                            u64 w = wv[xr][kx];
#pragma unroll
                            for (int j = 0; j < 7; j++)
                                acc0[j] = fma2(w, (kx & 1) ? po[j + (kx >> 1)] : pe[j + (kx >> 1)], acc0[j]);
                        }
                    }
                    if (xr >= 1) {
#pragma unroll
                        for (int kx = 0; kx < 5; kx++) {
                            u64 w = wv[xr - 1][kx];
#pragma unroll
                            for (int j = 0; j < 7; j++)
                                acc1[j] = fma2(w, (kx & 1) ? po[j + (kx >> 1)] : pe[j + (kx >> 1)], acc1[j]);
                        }
                    }
                }
            }
            float bv = s_b1[ch];
            float* yrow = s_y1[img] + (ch * 14 + py) * 20 + 7 * h;
#pragma unroll
            for (int j = 0; j < 7; j++) {
                float a0, a1, c0, c1;
                upk(acc0[j], a0, a1); upk(acc1[j], c0, c1);
                float m = fmaxf(fmaxf(a0, a1), fmaxf(c0, c1)) + bv;
                yrow[j] = fmaxf(m, 0.f);
            }
        }
        __syncthreads();
        if (img == 0) {
            // reload s_x with image 1
            const float4* xg = (const float4*)(x + (size_t)(b0i + 1) * 3072);
            for (int g = tid; g < 768; g += 192) {
                float4 v = xg[g];
                int gr = g >> 3, c4 = g & 7;
                *(float4*)(s_x + gr * 36 + c4 * 4) = v;
            }
            __syncthreads();
        }
    }

    // ---- conv2 full depth: 160 tasks = (img, ch, pooled row) ----
    if (tid < 160) {
        int img = tid / 80;
        int r2 = tid % 80, ch2 = r2 / 5, py2 = r2 % 5;
        u64 b0[5], b1[5];
#pragma unroll
        for (int j = 0; j < 5; j++) { b0[j] = 0ull; b1[j] = 0ull; }
#pragma unroll 1
        for (int ic = 0; ic < 6; ic++) {
            const float2* wb = s_w2p + (ch2 * 6 + ic) * 25;
            u64 wv[5][5];
#pragma unroll
            for (int xr = 0; xr < 6; xr++) {
                const u64* rp = (const u64*)(s_y1[img] + (ic * 14 + 2 * py2 + xr) * 20);
                u64 pe[7]; float xl[7], xh[7];
#pragma unroll
                for (int m = 0; m < 7; m++) { pe[m] = rp[m]; upk(pe[m], xl[m], xh[m]); }
                u64 po[6];
#pragma unroll
                for (int m = 0; m < 6; m++) po[m] = pk(xh[m], xl[m + 1]);
                if (xr < 5) {
#pragma unroll
                    for (int k = 0; k < 5; k++) wv[xr][k] = *(const u64*)&wb[xr * 5 + k];
#pragma unroll
                    for (int kx = 0; kx < 5; kx++) {
                        u64 w = wv[xr][kx];
#pragma unroll
                        for (int j = 0; j < 5; j++)
                            b0[j] = fma2(w, (kx & 1) ? po[j + (kx >> 1)] : pe[j + (kx >> 1)], b0[j]);
                    }
                }
                if (xr >= 1) {
#pragma unroll
                    for (int kx = 0; kx < 5; kx++) {
                        u64 w = wv[xr - 1][kx];
#pragma unroll
                        for (int j = 0; j < 5; j++)
                            b1[j] = fma2(w, (kx & 1) ? po[j + (kx >> 1)] : pe[j + (kx >> 1)], b1[j]);
                    }
                }
            }
        }
        float bv = s_b2[ch2];
        float* xfp = s_xf[img] + ch2 * 25 + py2 * 5;
        float* gxf = g_xf + (size_t)(b0i + img) * 400 + ch2 * 25 + py2 * 5;
#pragma unroll
        for (int j = 0; j < 5; j++) {
            float a0, a1, c0, c1;
            upk(b0[j], a0, a1); upk(b1[j], c0, c1);
            float v = fmaxf(fmaxf(a0, a1), fmaxf(c0, c1)) + bv;
            v = fmaxf(v, 0.f);
            xfp[j] = v; gxf[j] = v;
        }
    }
    __syncthreads();

    // ---- h = Ws @ xf + bs : 2 img x 10 outputs x 8 lanes = 160 threads ----
    if (tid < 160) {
        int img = tid / 80, r = tid % 80;
        int o = r >> 3, l = r & 7;
        const float* wr = g_T2 + o * 400;
        const float* xfv = s_xf[img];
        float s = 0.f;
        for (int j = l; j < 400; j += 8) s = fmaf(wr[j], xfv[j], s);
        s += __shfl_down_sync(0xffffffffu, s, 4, 8);
        s += __shfl_down_sync(0xffffffffu, s, 2, 8);
        s += __shfl_down_sync(0xffffffffu, s, 1, 8);
        if (l == 0) hs[img][o] = s + g_b3[o];
    }
    __syncthreads();

    // shapes = relu(h) @ sw4.T + sb4 : 8 threads
    if (tid < 8) {
        int img = tid >> 2, c = tid & 3;
        float s = sb4[c];
#pragma unroll
        for (int o = 0; o < 10; o++)
            s = fmaf(fmaxf(hs[img][o], 0.f), sw4[c * 10 + o], s);
        shp[img][c] = s;
        out[(size_t)(b0i + img) * 4 + c] = s;
    }
    __syncthreads();

    // routing: 2 threads, one per image
    if (tid < 2) {
        int img = tid, b = b0i + img;
        int pred = 0;
        float best = shp[img][0];
#pragma unroll
        for (int k = 1; k < 4; k++)
            if (shp[img][k] > best) { best = shp[img][k]; pred = k; }
        const int widths[4] = {3, 5, 6, 5};
        int w = widths[pred];
        int val = (b << 2) | pred;
        int slot = b & 31;
        for (int c = 0; c < w; c++) atomicMax(&g_last[c * 32 + slot], val);
    }
}

// ---------------------------------------------------------------------------
// out[b][c] = covered(c) ? dot(xf[b], We_row) + be : 0 ; We rows built inline.
// ---------------------------------------------------------------------------
__global__ void __launch_bounds__(256)
k_out(const float* __restrict__ ew4, const float* __restrict__ eb4,
      float* __restrict__ out) {
    __shared__ __align__(16) float wsel[6 * 400];
    __shared__ float bsel[6];
    __shared__ int   psel[6];
    __shared__ float sw4e[240];
    int tid = threadIdx.x;
    if (tid < 240) sw4e[tid] = ew4[tid];
    if (tid < 6) {
        int mx = -1;
#pragma unroll
        for (int s = 0; s < 32; s++) mx = max(mx, g_last[tid * 32 + s]);
        psel[tid] = mx;
    }
    __syncthreads();
    for (int idx = tid; idx < 2400; idx += 256) {
        int c = idx / 400, j = idx - c * 400;
        int p = psel[c];
        float s = 0.f;
        if (p >= 0) {
            int e = p & 3;
            const float* w4r = sw4e + e * 60 + c * 10;
            const float* t2 = g_T2 + (1 + e) * 10 * 400 + j;
#pragma unroll
            for (int k = 0; k < 10; k++) s = fmaf(w4r[k], t2[k * 400], s);
        }
        wsel[idx] = s;
    }
    if (tid < 6) {
        int p = psel[tid];
        float s = 0.f;
        if (p >= 0) {
            int e = p & 3;
            s = eb4[e * 6 + tid];
#pragma unroll
            for (int k = 0; k < 10; k++)
                s = fmaf(sw4e[e * 60 + tid * 10 + k], g_b3[(1 + e) * 10 + k], s);
        }
        bsel[tid] = s;
    }
    __syncthreads();
    int c = tid & 7, r = tid >> 3;
    int b = blockIdx.x * 32 + r;
    if (c < 6) {
        const float4* xfp = (const float4*)(g_xf + (size_t)b * 400);
        const float4* wr = (const float4*)(wsel + c * 400);
        float s = bsel[c];
        for (int j = 0; j < 100; j++) {
            float4 xv = xfp[j], wv = wr[j];
            s = fmaf(xv.x, wv.x, s);
            s = fmaf(xv.y, wv.y, s);
            s = fmaf(xv.z, wv.z, s);
            s = fmaf(xv.w, wv.w, s);
        }
        out[(size_t)B_TOTAL * 4 + (size_t)b * 6 + c] = s;
    }
}

// ---------------------------------------------------------------------------
extern "C" void kernel_launch(void* const* d_in, const int* in_sizes, int n_in,
                              void* d_out, int out_size) {
    const float* x    = (const float*)d_in[0];
    const float* c1w  = (const float*)d_in[1];
    const float* c1b  = (const float*)d_in[2];
    const float* c2w  = (const float*)d_in[3];
    const float* c2b  = (const float*)d_in[4];
    const float* sw1  = (const float*)d_in[5];
    const float* sb1  = (const float*)d_in[6];
    const float* sw2  = (const float*)d_in[7];
    const float* sb2  = (const float*)d_in[8];
    const float* sw3  = (const float*)d_in[9];
    const float* sb3  = (const float*)d_in[10];
    const float* sw4  = (const float*)d_in[11];
    const float* sb4  = (const float*)d_in[12];
    const float* ew1  = (const float*)d_in[13];
    const float* eb1  = (const float*)d_in[14];
    const float* ew2  = (const float*)d_in[15];
    const float* eb2  = (const float*)d_in[16];
    const float* ew3  = (const float*)d_in[17];
    const float* eb3  = (const float*)d_in[18];
    const float* ew4  = (const float*)d_in[19];
    const float* eb4  = (const float*)d_in[20];
    float* out = (float*)d_out;

    kc_prep<<<80, 256>>>(sw1, sb1, sw2, sb2, sw3, sb3,
                         ew1, eb1, ew2, eb2, ew3, eb3);
    k_main<<<B_TOTAL / 2, 192>>>(x, c1w, c1b, c2w, c2b, sw4, sb4, out);
    k_out<<<B_TOTAL / 32, 256>>>(ew4, eb4, out);
}